// round 1
// baseline (speedup 1.0000x reference)
#include <cuda_runtime.h>
#include <math.h>

#define NN      8192
#define FIN     512
#define HH      8
#define C1      8
#define HC      64      // H*C1
#define NC      16
#define EE      262144
#define ETOT    (EE + NN)   // with self-loops
#define NEG     0.2f

// ---------------- device scratch (no allocations allowed) ----------------
__device__ int   g_deg[NN];
__device__ int   g_off[NN + 1];
__device__ int   g_cur[NN];
__device__ int   g_csr[ETOT];

__device__ float g_h   [NN * HC];   // layer1 transformed features
__device__ float g_als1[NN * HH];
__device__ float g_ald1[NN * HH];
__device__ float g_h1  [NN * HC];   // layer1 output (post-ELU)
__device__ float g_h2  [NN * NC];   // layer2 transformed
__device__ float g_als2[NN];
__device__ float g_ald2[NN];
__device__ float g_z   [NN * NC];   // layer2 output (pre-softmax)

// ---------------- CSR build ----------------
__global__ void k_zero_deg() {
    int i = blockIdx.x * blockDim.x + threadIdx.x;
    if (i < NN) g_deg[i] = 0;
}

__global__ void k_count(const int* __restrict__ ei) {
    int e = blockIdx.x * blockDim.x + threadIdx.x;
    if (e >= ETOT) return;
    int dst = (e < EE) ? ei[EE + e] : (e - EE);
    atomicAdd(&g_deg[dst], 1);
}

__global__ void k_scan() {
    __shared__ int part[1024];
    int t = threadIdx.x;
    int base = t * 8;
    int loc[8];
    int s = 0;
#pragma unroll
    for (int i = 0; i < 8; i++) { loc[i] = s; s += g_deg[base + i]; }
    part[t] = s;
    __syncthreads();
    for (int off = 1; off < 1024; off <<= 1) {
        int v = (t >= off) ? part[t - off] : 0;
        __syncthreads();
        part[t] += v;
        __syncthreads();
    }
    int pre = (t == 0) ? 0 : part[t - 1];
#pragma unroll
    for (int i = 0; i < 8; i++) {
        int o = pre + loc[i];
        g_off[base + i] = o;
        g_cur[base + i] = o;
    }
    if (t == 1023) g_off[NN] = part[1023];
}

__global__ void k_scatter(const int* __restrict__ ei) {
    int e = blockIdx.x * blockDim.x + threadIdx.x;
    if (e >= ETOT) return;
    int src, dst;
    if (e < EE) { src = ei[e]; dst = ei[EE + e]; }
    else        { src = e - EE; dst = src; }
    int pos = atomicAdd(&g_cur[dst], 1);
    g_csr[pos] = src;
}

// ---------------- GEMM1: h = x @ W1  (8192x512 @ 512x64) ----------------
__global__ void k_gemm1(const float* __restrict__ x, const float* __restrict__ W1) {
    __shared__ float xs[64][17];
    __shared__ float ws[16][64];
    int tid = threadIdx.x;
    int row0 = blockIdx.x * 64;
    int tr = tid >> 4;        // 0..15
    int tc = tid & 15;        // 0..15
    float acc[4][4];
#pragma unroll
    for (int i = 0; i < 4; i++)
#pragma unroll
        for (int j = 0; j < 4; j++) acc[i][j] = 0.f;

    int lr = tid >> 2, lc = (tid & 3) * 4;       // x-load: 64 rows x 4 groups
    int wr = tid >> 4, wc = (tid & 15) * 4;      // w-load: 16 rows x 16 groups

    for (int k0 = 0; k0 < FIN; k0 += 16) {
        float4 xv = *(const float4*)&x[(size_t)(row0 + lr) * FIN + k0 + lc];
        xs[lr][lc + 0] = xv.x; xs[lr][lc + 1] = xv.y;
        xs[lr][lc + 2] = xv.z; xs[lr][lc + 3] = xv.w;
        float4 wv = *(const float4*)&W1[(size_t)(k0 + wr) * HC + wc];
        *(float4*)&ws[wr][wc] = wv;
        __syncthreads();
#pragma unroll
        for (int kk = 0; kk < 16; kk++) {
            float a[4], b[4];
#pragma unroll
            for (int i = 0; i < 4; i++) a[i] = xs[tr * 4 + i][kk];
#pragma unroll
            for (int j = 0; j < 4; j++) b[j] = ws[kk][tc * 4 + j];
#pragma unroll
            for (int i = 0; i < 4; i++)
#pragma unroll
                for (int j = 0; j < 4; j++) acc[i][j] = fmaf(a[i], b[j], acc[i][j]);
        }
        __syncthreads();
    }
#pragma unroll
    for (int i = 0; i < 4; i++) {
        int r = row0 + tr * 4 + i;
#pragma unroll
        for (int j = 0; j < 4; j++)
            g_h[(size_t)r * HC + tc * 4 + j] = acc[i][j];
    }
}

// ---------------- per-node attention logits, layer 1 ----------------
__global__ void k_attn_pre1(const float* __restrict__ a_src, const float* __restrict__ a_dst) {
    __shared__ float as[HC], ad[HC];
    if (threadIdx.x < HC) { as[threadIdx.x] = a_src[threadIdx.x]; ad[threadIdx.x] = a_dst[threadIdx.x]; }
    __syncthreads();
    int n = blockIdx.x * blockDim.x + threadIdx.x;
    if (n >= NN) return;
    const float* hp = &g_h[(size_t)n * HC];
#pragma unroll
    for (int h = 0; h < HH; h++) {
        float s = 0.f, d = 0.f;
#pragma unroll
        for (int c = 0; c < C1; c++) {
            float hv = hp[h * C1 + c];
            s = fmaf(hv, as[h * C1 + c], s);
            d = fmaf(hv, ad[h * C1 + c], d);
        }
        g_als1[n * HH + h] = s;
        g_ald1[n * HH + h] = d;
    }
}

__device__ __forceinline__ float warp_max(float v) {
#pragma unroll
    for (int o = 16; o; o >>= 1) v = fmaxf(v, __shfl_xor_sync(0xffffffffu, v, o));
    return v;
}
__device__ __forceinline__ float warp_sum(float v) {
#pragma unroll
    for (int o = 16; o; o >>= 1) v += __shfl_xor_sync(0xffffffffu, v, o);
    return v;
}

// ---------------- aggregation layer 1: block per node, warp per head ----------------
__global__ void k_agg1(const float* __restrict__ b1) {
    int n = blockIdx.x;
    int wid = threadIdx.x >> 5;   // head
    int lane = threadIdx.x & 31;
    int o0 = g_off[n];
    int deg = g_off[n + 1] - o0;
    float ald = g_ald1[n * HH + wid];

    float m = -INFINITY;
    for (int j = lane; j < deg; j += 32) {
        int s = g_csr[o0 + j];
        float v = g_als1[s * HH + wid] + ald;
        v = (v > 0.f) ? v : NEG * v;
        m = fmaxf(m, v);
    }
    m = warp_max(m);

    float sumex = 0.f;
    float acc[C1];
#pragma unroll
    for (int c = 0; c < C1; c++) acc[c] = 0.f;
    for (int j = lane; j < deg; j += 32) {
        int s = g_csr[o0 + j];
        float v = g_als1[s * HH + wid] + ald;
        v = (v > 0.f) ? v : NEG * v;
        float ex = expf(v - m);
        sumex += ex;
        const float* hp = &g_h[(size_t)s * HC + wid * C1];
#pragma unroll
        for (int c = 0; c < C1; c++) acc[c] = fmaf(ex, hp[c], acc[c]);
    }
    sumex = warp_sum(sumex);
#pragma unroll
    for (int c = 0; c < C1; c++) acc[c] = warp_sum(acc[c]);

    if (lane == 0) {
        float inv = 1.f / sumex;
#pragma unroll
        for (int c = 0; c < C1; c++) {
            float o = acc[c] * inv + b1[wid * C1 + c];
            o = (o > 0.f) ? o : (expf(o) - 1.f);   // ELU
            g_h1[(size_t)n * HC + wid * C1 + c] = o;
        }
    }
}

// ---------------- layer 2 transform: h2 = h1 @ W2, attention logits ----------------
__global__ void k_l2t(const float* __restrict__ W2,
                      const float* __restrict__ a_src2, const float* __restrict__ a_dst2) {
    __shared__ float w[HC * NC];
    __shared__ float as2[NC], ad2[NC];
    for (int i = threadIdx.x; i < HC * NC; i += blockDim.x) w[i] = W2[i];
    if (threadIdx.x < NC) { as2[threadIdx.x] = a_src2[threadIdx.x]; ad2[threadIdx.x] = a_dst2[threadIdx.x]; }
    __syncthreads();
    int n = blockIdx.x * blockDim.x + threadIdx.x;
    if (n >= NN) return;
    const float* hp = &g_h1[(size_t)n * HC];
    float out[NC];
#pragma unroll
    for (int c = 0; c < NC; c++) out[c] = 0.f;
#pragma unroll 8
    for (int k = 0; k < HC; k++) {
        float hv = hp[k];
#pragma unroll
        for (int c = 0; c < NC; c++) out[c] = fmaf(hv, w[k * NC + c], out[c]);
    }
    float s = 0.f, d = 0.f;
#pragma unroll
    for (int c = 0; c < NC; c++) {
        g_h2[(size_t)n * NC + c] = out[c];
        s = fmaf(out[c], as2[c], s);
        d = fmaf(out[c], ad2[c], d);
    }
    g_als2[n] = s;
    g_ald2[n] = d;
}

// ---------------- aggregation layer 2: warp per node ----------------
__global__ void k_agg2(const float* __restrict__ b2) {
    int n = blockIdx.x * 8 + (threadIdx.x >> 5);
    int lane = threadIdx.x & 31;
    if (n >= NN) return;
    int o0 = g_off[n];
    int deg = g_off[n + 1] - o0;
    float ald = g_ald2[n];

    float m = -INFINITY;
    for (int j = lane; j < deg; j += 32) {
        int s = g_csr[o0 + j];
        float v = g_als2[s] + ald;
        v = (v > 0.f) ? v : NEG * v;
        m = fmaxf(m, v);
    }
    m = warp_max(m);

    float sumex = 0.f;
    float acc[NC];
#pragma unroll
    for (int c = 0; c < NC; c++) acc[c] = 0.f;
    for (int j = lane; j < deg; j += 32) {
        int s = g_csr[o0 + j];
        float v = g_als2[s] + ald;
        v = (v > 0.f) ? v : NEG * v;
        float ex = expf(v - m);
        sumex += ex;
        const float* hp = &g_h2[(size_t)s * NC];
#pragma unroll
        for (int c = 0; c < NC; c++) acc[c] = fmaf(ex, hp[c], acc[c]);
    }
    sumex = warp_sum(sumex);
#pragma unroll
    for (int c = 0; c < NC; c++) acc[c] = warp_sum(acc[c]);

    if (lane == 0) {
        float inv = 1.f / sumex;
#pragma unroll
        for (int c = 0; c < NC; c++)
            g_z[(size_t)n * NC + c] = acc[c] * inv + b2[c];
    }
}

// ---------------- log_softmax to output ----------------
__global__ void k_logsoftmax(float* __restrict__ out) {
    int n = blockIdx.x * blockDim.x + threadIdx.x;
    if (n >= NN) return;
    const float* zp = &g_z[(size_t)n * NC];
    float zv[NC];
    float m = -INFINITY;
#pragma unroll
    for (int c = 0; c < NC; c++) { zv[c] = zp[c]; m = fmaxf(m, zv[c]); }
    float s = 0.f;
#pragma unroll
    for (int c = 0; c < NC; c++) s += expf(zv[c] - m);
    float lse = m + logf(s);
#pragma unroll
    for (int c = 0; c < NC; c++) out[(size_t)n * NC + c] = zv[c] - lse;
}

// ---------------- Gram: G = z @ z.T  (8192 x 8192, K=16) ----------------
__global__ void k_gram(float* __restrict__ out) {
    __shared__ float zrT[NC][128];
    __shared__ float zcT[NC][128];
    int tid = threadIdx.x;
    int row0 = blockIdx.y * 128;
    int col0 = blockIdx.x * 128;

    {
        int r = tid >> 1;
        int kg = (tid & 1) * 8;
        float4 v0 = *(const float4*)&g_z[(size_t)(row0 + r) * NC + kg];
        float4 v1 = *(const float4*)&g_z[(size_t)(row0 + r) * NC + kg + 4];
        zrT[kg + 0][r] = v0.x; zrT[kg + 1][r] = v0.y; zrT[kg + 2][r] = v0.z; zrT[kg + 3][r] = v0.w;
        zrT[kg + 4][r] = v1.x; zrT[kg + 5][r] = v1.y; zrT[kg + 6][r] = v1.z; zrT[kg + 7][r] = v1.w;
        float4 u0 = *(const float4*)&g_z[(size_t)(col0 + r) * NC + kg];
        float4 u1 = *(const float4*)&g_z[(size_t)(col0 + r) * NC + kg + 4];
        zcT[kg + 0][r] = u0.x; zcT[kg + 1][r] = u0.y; zcT[kg + 2][r] = u0.z; zcT[kg + 3][r] = u0.w;
        zcT[kg + 4][r] = u1.x; zcT[kg + 5][r] = u1.y; zcT[kg + 6][r] = u1.z; zcT[kg + 7][r] = u1.w;
    }
    __syncthreads();

    int ty = tid >> 4, tx = tid & 15;
    int rr = ty * 8, cc = tx * 8;
    float acc[8][8];
#pragma unroll
    for (int i = 0; i < 8; i++)
#pragma unroll
        for (int j = 0; j < 8; j++) acc[i][j] = 0.f;

#pragma unroll
    for (int k = 0; k < NC; k++) {
        float a[8], b[8];
#pragma unroll
        for (int i = 0; i < 8; i++) a[i] = zrT[k][rr + i];
#pragma unroll
        for (int j = 0; j < 8; j++) b[j] = zcT[k][cc + j];
#pragma unroll
        for (int i = 0; i < 8; i++)
#pragma unroll
            for (int j = 0; j < 8; j++) acc[i][j] = fmaf(a[i], b[j], acc[i][j]);
    }

#pragma unroll
    for (int i = 0; i < 8; i++) {
        size_t base = (size_t)(row0 + rr + i) * NN + col0 + cc;
        float4 v0 = make_float4(acc[i][0], acc[i][1], acc[i][2], acc[i][3]);
        float4 v1 = make_float4(acc[i][4], acc[i][5], acc[i][6], acc[i][7]);
        *(float4*)&out[base]     = v0;
        *(float4*)&out[base + 4] = v1;
    }
}

// ---------------- launch ----------------
extern "C" void kernel_launch(void* const* d_in, const int* in_sizes, int n_in,
                              void* d_out, int out_size) {
    const float* x      = (const float*)d_in[0];
    const int*   ei     = (const int*)  d_in[1];
    const float* W1     = (const float*)d_in[2];
    const float* a_src1 = (const float*)d_in[3];
    const float* a_dst1 = (const float*)d_in[4];
    const float* b1     = (const float*)d_in[5];
    const float* W2     = (const float*)d_in[6];
    const float* a_src2 = (const float*)d_in[7];
    const float* a_dst2 = (const float*)d_in[8];
    const float* b2     = (const float*)d_in[9];
    float* out = (float*)d_out;

    k_zero_deg<<<NN / 256, 256>>>();
    k_count<<<(ETOT + 255) / 256, 256>>>(ei);
    k_scan<<<1, 1024>>>();
    k_scatter<<<(ETOT + 255) / 256, 256>>>(ei);

    k_gemm1<<<NN / 64, 256>>>(x, W1);
    k_attn_pre1<<<NN / 256, 256>>>(a_src1, a_dst1);
    k_agg1<<<NN, 256>>>(b1);

    k_l2t<<<NN / 256, 256>>>(W2, a_src2, a_dst2);
    k_agg2<<<NN / 8, 256>>>(b2);

    k_logsoftmax<<<NN / 256, 256>>>(out);
    k_gram<<<dim3(NN / 128, NN / 128), 256>>>(out + (size_t)NN * NC);
}

// round 3
// speedup vs baseline: 1.3943x; 1.3943x over previous
#include <cuda_runtime.h>
#include <math.h>

#define NN      8192
#define FIN     512
#define HH      8
#define C1      8
#define HC      64      // H*C1
#define NC      16
#define EE      262144
#define ETOT    (EE + NN)   // with self-loops
#define NEG     0.2f

// ---------------- packed f32x2 helpers (Blackwell FFMA2 path) ----------------
__device__ __forceinline__ float2 ffma2(float2 a, float2 b, float2 c) {
    unsigned long long ra = *reinterpret_cast<unsigned long long*>(&a);
    unsigned long long rb = *reinterpret_cast<unsigned long long*>(&b);
    unsigned long long rc = *reinterpret_cast<unsigned long long*>(&c);
    unsigned long long rd;
    asm("fma.rn.f32x2 %0, %1, %2, %3;" : "=l"(rd) : "l"(ra), "l"(rb), "l"(rc));
    return *reinterpret_cast<float2*>(&rd);
}
__device__ __forceinline__ float2 add2(float2 a, float2 b) {
    unsigned long long ra = *reinterpret_cast<unsigned long long*>(&a);
    unsigned long long rb = *reinterpret_cast<unsigned long long*>(&b);
    unsigned long long rd;
    asm("add.rn.f32x2 %0, %1, %2;" : "=l"(rd) : "l"(ra), "l"(rb));
    return *reinterpret_cast<float2*>(&rd);
}
__device__ __forceinline__ float2 shfl_xor_f2(float2 v, int m) {
    float2 r;
    r.x = __shfl_xor_sync(0xffffffffu, v.x, m);
    r.y = __shfl_xor_sync(0xffffffffu, v.y, m);
    return r;
}

// ---------------- device scratch (no allocations allowed) ----------------
__device__ int   g_deg[NN];
__device__ int   g_off[NN + 1];
__device__ int   g_cur[NN];
__device__ int   g_csr[ETOT];

__device__ float g_h   [NN * HC];   // layer1 transformed features
__device__ float g_als1[NN * HH];
__device__ float g_ald1[NN * HH];
__device__ float g_h1  [NN * HC];   // layer1 output (post-ELU)
__device__ float g_h2  [NN * NC];   // layer2 transformed
__device__ float g_als2[NN];
__device__ float g_ald2[NN];
__device__ float g_z   [NN * NC];   // layer2 output (pre-softmax)

// ---------------- CSR build ----------------
__global__ void k_zero_deg() {
    int i = blockIdx.x * blockDim.x + threadIdx.x;
    if (i < NN) g_deg[i] = 0;
}

__global__ void k_count(const int* __restrict__ ei) {
    int e = blockIdx.x * blockDim.x + threadIdx.x;
    if (e >= ETOT) return;
    int dst = (e < EE) ? ei[EE + e] : (e - EE);
    atomicAdd(&g_deg[dst], 1);
}

__global__ void k_scan() {
    __shared__ int part[1024];
    int t = threadIdx.x;
    int base = t * 8;
    int loc[8];
    int s = 0;
#pragma unroll
    for (int i = 0; i < 8; i++) { loc[i] = s; s += g_deg[base + i]; }
    part[t] = s;
    __syncthreads();
    for (int off = 1; off < 1024; off <<= 1) {
        int v = (t >= off) ? part[t - off] : 0;
        __syncthreads();
        part[t] += v;
        __syncthreads();
    }
    int pre = (t == 0) ? 0 : part[t - 1];
#pragma unroll
    for (int i = 0; i < 8; i++) {
        int o = pre + loc[i];
        g_off[base + i] = o;
        g_cur[base + i] = o;
    }
    if (t == 1023) g_off[NN] = part[1023];
}

__global__ void k_scatter(const int* __restrict__ ei) {
    int e = blockIdx.x * blockDim.x + threadIdx.x;
    if (e >= ETOT) return;
    int src, dst;
    if (e < EE) { src = ei[e]; dst = ei[EE + e]; }
    else        { src = e - EE; dst = src; }
    int pos = atomicAdd(&g_cur[dst], 1);
    g_csr[pos] = src;
}

// ---------------- GEMM1: h = x @ W1  (8192x512 @ 512x64), FFMA2 inner ----------------
__global__ void k_gemm1(const float* __restrict__ x, const float* __restrict__ W1) {
    __shared__ float xs[64][17];
    __shared__ float ws[16][64];
    int tid = threadIdx.x;
    int row0 = blockIdx.x * 64;
    int tr = tid >> 4;        // 0..15
    int tc = tid & 15;        // 0..15
    float2 acc[4][2];
#pragma unroll
    for (int i = 0; i < 4; i++)
#pragma unroll
        for (int j = 0; j < 2; j++) acc[i][j] = make_float2(0.f, 0.f);

    int lr = tid >> 2, lc = (tid & 3) * 4;       // x-load: 64 rows x 4 groups
    int wr = tid >> 4, wc = (tid & 15) * 4;      // w-load: 16 rows x 16 groups

    for (int k0 = 0; k0 < FIN; k0 += 16) {
        float4 xv = *(const float4*)&x[(size_t)(row0 + lr) * FIN + k0 + lc];
        xs[lr][lc + 0] = xv.x; xs[lr][lc + 1] = xv.y;
        xs[lr][lc + 2] = xv.z; xs[lr][lc + 3] = xv.w;
        float4 wv = *(const float4*)&W1[(size_t)(k0 + wr) * HC + wc];
        *(float4*)&ws[wr][wc] = wv;
        __syncthreads();
#pragma unroll
        for (int kk = 0; kk < 16; kk++) {
            float2 b0 = *(float2*)&ws[kk][tc * 4];
            float2 b1 = *(float2*)&ws[kk][tc * 4 + 2];
#pragma unroll
            for (int i = 0; i < 4; i++) {
                float av = xs[tr * 4 + i][kk];
                float2 ad = make_float2(av, av);
                acc[i][0] = ffma2(ad, b0, acc[i][0]);
                acc[i][1] = ffma2(ad, b1, acc[i][1]);
            }
        }
        __syncthreads();
    }
#pragma unroll
    for (int i = 0; i < 4; i++) {
        int r = row0 + tr * 4 + i;
        float4 v = make_float4(acc[i][0].x, acc[i][0].y, acc[i][1].x, acc[i][1].y);
        *(float4*)&g_h[(size_t)r * HC + tc * 4] = v;
    }
}

// ---------------- per-node attention logits, layer 1 ----------------
__global__ void k_attn_pre1(const float* __restrict__ a_src, const float* __restrict__ a_dst) {
    __shared__ float as[HC], ad[HC];
    if (threadIdx.x < HC) { as[threadIdx.x] = a_src[threadIdx.x]; ad[threadIdx.x] = a_dst[threadIdx.x]; }
    __syncthreads();
    int n = blockIdx.x * blockDim.x + threadIdx.x;
    if (n >= NN) return;
    const float* hp = &g_h[(size_t)n * HC];
#pragma unroll
    for (int h = 0; h < HH; h++) {
        float s = 0.f, d = 0.f;
#pragma unroll
        for (int c = 0; c < C1; c++) {
            float hv = hp[h * C1 + c];
            s = fmaf(hv, as[h * C1 + c], s);
            d = fmaf(hv, ad[h * C1 + c], d);
        }
        g_als1[n * HH + h] = s;
        g_ald1[n * HH + h] = d;
    }
}

// ---------------- aggregation layer 1: warp per node, all heads, single pass ----------------
__global__ void k_agg1(const float* __restrict__ b1) {
    int warp = threadIdx.x >> 5;
    int lane = threadIdx.x & 31;
    int n = blockIdx.x * 8 + warp;
    int o0 = g_off[n];
    int deg = g_off[n + 1] - o0;

    float4 ad0 = *(const float4*)&g_ald1[n * HH];
    float4 ad1 = *(const float4*)&g_ald1[n * HH + 4];
    float ald[8] = {ad0.x, ad0.y, ad0.z, ad0.w, ad1.x, ad1.y, ad1.z, ad1.w};

    float2 acc[32];
#pragma unroll
    for (int i = 0; i < 32; i++) acc[i] = make_float2(0.f, 0.f);
    float sumex[8];
#pragma unroll
    for (int h = 0; h < 8; h++) sumex[h] = 0.f;

    for (int j = lane; j < deg; j += 32) {
        int s = g_csr[o0 + j];
        float4 s0 = *(const float4*)&g_als1[s * HH];
        float4 s1 = *(const float4*)&g_als1[s * HH + 4];
        float e[8] = {s0.x, s0.y, s0.z, s0.w, s1.x, s1.y, s1.z, s1.w};
        float ex[8];
#pragma unroll
        for (int h = 0; h < 8; h++) {
            float v = e[h] + ald[h];
            v = fmaxf(v, NEG * v);      // leaky relu (valid since NEG < 1)
            ex[h] = __expf(v);
            sumex[h] += ex[h];
        }
        const float4* hp = (const float4*)&g_h[(size_t)s * HC];
#pragma unroll
        for (int h = 0; h < 8; h++) {
            float2 exd = make_float2(ex[h], ex[h]);
            float4 h0 = hp[h * 2 + 0];
            float4 h1 = hp[h * 2 + 1];
            acc[h * 4 + 0] = ffma2(exd, make_float2(h0.x, h0.y), acc[h * 4 + 0]);
            acc[h * 4 + 1] = ffma2(exd, make_float2(h0.z, h0.w), acc[h * 4 + 1]);
            acc[h * 4 + 2] = ffma2(exd, make_float2(h1.x, h1.y), acc[h * 4 + 2]);
            acc[h * 4 + 3] = ffma2(exd, make_float2(h1.z, h1.w), acc[h * 4 + 3]);
        }
    }

    // reduce-scatter: after 5 steps lane l owns channel pair {2l, 2l+1} in acc[0]
    {
        // step 0: o=16, 16 pairs
#pragma unroll
        for (int i = 0; i < 16; i++) {
            bool hi = (lane & 16) != 0;
            float2 send = hi ? acc[i] : acc[i + 16];
            float2 got = shfl_xor_f2(send, 16);
            float2 keep = hi ? acc[i + 16] : acc[i];
            acc[i] = add2(keep, got);
        }
#pragma unroll
        for (int i = 0; i < 8; i++) {
            bool hi = (lane & 8) != 0;
            float2 send = hi ? acc[i] : acc[i + 8];
            float2 got = shfl_xor_f2(send, 8);
            float2 keep = hi ? acc[i + 8] : acc[i];
            acc[i] = add2(keep, got);
        }
#pragma unroll
        for (int i = 0; i < 4; i++) {
            bool hi = (lane & 4) != 0;
            float2 send = hi ? acc[i] : acc[i + 4];
            float2 got = shfl_xor_f2(send, 4);
            float2 keep = hi ? acc[i + 4] : acc[i];
            acc[i] = add2(keep, got);
        }
#pragma unroll
        for (int i = 0; i < 2; i++) {
            bool hi = (lane & 2) != 0;
            float2 send = hi ? acc[i] : acc[i + 2];
            float2 got = shfl_xor_f2(send, 2);
            float2 keep = hi ? acc[i + 2] : acc[i];
            acc[i] = add2(keep, got);
        }
        {
            bool hi = (lane & 1) != 0;
            float2 send = hi ? acc[0] : acc[1];
            float2 got = shfl_xor_f2(send, 1);
            float2 keep = hi ? acc[1] : acc[0];
            acc[0] = add2(keep, got);
        }
    }

    // sumex reduce-scatter over heads (bits 4,3,2), then full-add over bits 1,0
    {
#pragma unroll
        for (int i = 0; i < 4; i++) {
            bool hi = (lane & 16) != 0;
            float send = hi ? sumex[i] : sumex[i + 4];
            float got = __shfl_xor_sync(0xffffffffu, send, 16);
            float keep = hi ? sumex[i + 4] : sumex[i];
            sumex[i] = keep + got;
        }
#pragma unroll
        for (int i = 0; i < 2; i++) {
            bool hi = (lane & 8) != 0;
            float send = hi ? sumex[i] : sumex[i + 2];
            float got = __shfl_xor_sync(0xffffffffu, send, 8);
            float keep = hi ? sumex[i + 2] : sumex[i];
            sumex[i] = keep + got;
        }
        {
            bool hi = (lane & 4) != 0;
            float send = hi ? sumex[0] : sumex[1];
            float got = __shfl_xor_sync(0xffffffffu, send, 4);
            float keep = hi ? sumex[1] : sumex[0];
            sumex[0] = keep + got;
        }
    }
    float se = sumex[0];
    se += __shfl_xor_sync(0xffffffffu, se, 2);
    se += __shfl_xor_sync(0xffffffffu, se, 1);
    // lane owns head (lane>>2)&7 == head of channels {2*lane, 2*lane+1}

    float inv = 1.f / se;
    float c0 = acc[0].x * inv + b1[2 * lane];
    float c1 = acc[0].y * inv + b1[2 * lane + 1];
    c0 = (c0 > 0.f) ? c0 : (__expf(c0) - 1.f);   // ELU
    c1 = (c1 > 0.f) ? c1 : (__expf(c1) - 1.f);
    *(float2*)&g_h1[(size_t)n * HC + 2 * lane] = make_float2(c0, c1);
}

// ---------------- layer 2 transform: h2 = h1 @ W2, attention logits ----------------
__global__ void k_l2t(const float* __restrict__ W2,
                      const float* __restrict__ a_src2, const float* __restrict__ a_dst2) {
    __shared__ float w[HC * NC];
    __shared__ float as2[NC], ad2[NC];
    for (int i = threadIdx.x; i < HC * NC; i += blockDim.x) w[i] = W2[i];
    if (threadIdx.x < NC) { as2[threadIdx.x] = a_src2[threadIdx.x]; ad2[threadIdx.x] = a_dst2[threadIdx.x]; }
    __syncthreads();
    int n = blockIdx.x * blockDim.x + threadIdx.x;
    if (n >= NN) return;
    const float* hp = &g_h1[(size_t)n * HC];
    float out[NC];
#pragma unroll
    for (int c = 0; c < NC; c++) out[c] = 0.f;
#pragma unroll 8
    for (int k = 0; k < HC; k++) {
        float hv = hp[k];
#pragma unroll
        for (int c = 0; c < NC; c++) out[c] = fmaf(hv, w[k * NC + c], out[c]);
    }
    float s = 0.f, d = 0.f;
#pragma unroll
    for (int c = 0; c < NC; c++) {
        g_h2[(size_t)n * NC + c] = out[c];
        s = fmaf(out[c], as2[c], s);
        d = fmaf(out[c], ad2[c], d);
    }
    g_als2[n] = s;
    g_ald2[n] = d;
}

// ---------------- layer 2 aggregation + log_softmax, fused: warp per node ----------------
__global__ void k_agg2(const float* __restrict__ b2, float* __restrict__ outls) {
    int warp = threadIdx.x >> 5;
    int lane = threadIdx.x & 31;
    int n = blockIdx.x * 8 + warp;
    int o0 = g_off[n];
    int deg = g_off[n + 1] - o0;
    float ald = g_ald2[n];

    float2 acc[8];
#pragma unroll
    for (int i = 0; i < 8; i++) acc[i] = make_float2(0.f, 0.f);
    float sumex = 0.f;

    for (int j = lane; j < deg; j += 32) {
        int s = g_csr[o0 + j];
        float v = g_als2[s] + ald;
        v = fmaxf(v, NEG * v);
        float ex = __expf(v);
        sumex += ex;
        float2 exd = make_float2(ex, ex);
        const float4* hp = (const float4*)&g_h2[(size_t)s * NC];
#pragma unroll
        for (int q = 0; q < 4; q++) {
            float4 hv = hp[q];
            acc[q * 2 + 0] = ffma2(exd, make_float2(hv.x, hv.y), acc[q * 2 + 0]);
            acc[q * 2 + 1] = ffma2(exd, make_float2(hv.z, hv.w), acc[q * 2 + 1]);
        }
    }

    // reduce-scatter over 8 pairs (bits 4,3,2) then full-add over bits 1,0
    {
#pragma unroll
        for (int i = 0; i < 4; i++) {
            bool hi = (lane & 16) != 0;
            float2 send = hi ? acc[i] : acc[i + 4];
            float2 got = shfl_xor_f2(send, 16);
            float2 keep = hi ? acc[i + 4] : acc[i];
            acc[i] = add2(keep, got);
        }
#pragma unroll
        for (int i = 0; i < 2; i++) {
            bool hi = (lane & 8) != 0;
            float2 send = hi ? acc[i] : acc[i + 2];
            float2 got = shfl_xor_f2(send, 8);
            float2 keep = hi ? acc[i + 2] : acc[i];
            acc[i] = add2(keep, got);
        }
        {
            bool hi = (lane & 4) != 0;
            float2 send = hi ? acc[0] : acc[1];
            float2 got = shfl_xor_f2(send, 4);
            float2 keep = hi ? acc[1] : acc[0];
            acc[0] = add2(keep, got);
        }
    }
    acc[0] = add2(acc[0], shfl_xor_f2(acc[0], 2));
    acc[0] = add2(acc[0], shfl_xor_f2(acc[0], 1));
    // lane owns channel pair p = (lane>>2)&7 -> channels {2p, 2p+1}, duplicated over 4 lanes

#pragma unroll
    for (int o = 16; o >= 1; o >>= 1) sumex += __shfl_xor_sync(0xffffffffu, sumex, o);

    int p = lane >> 2;
    float inv = 1.f / sumex;
    float z0 = acc[0].x * inv + b2[2 * p];
    float z1 = acc[0].y * inv + b2[2 * p + 1];

    // log_softmax over the 16 channels (each appears on 4 lanes)
    float m = fmaxf(z0, z1);
#pragma unroll
    for (int o = 16; o >= 1; o >>= 1) m = fmaxf(m, __shfl_xor_sync(0xffffffffu, m, o));
    float se2 = __expf(z0 - m) + __expf(z1 - m);
#pragma unroll
    for (int o = 16; o >= 1; o >>= 1) se2 += __shfl_xor_sync(0xffffffffu, se2, o);
    se2 *= 0.25f;   // each channel counted 4x
    float lse = m + __logf(se2);

    if ((lane & 3) == 0) {
        *(float2*)&g_z[(size_t)n * NC + 2 * p] = make_float2(z0, z1);
        *(float2*)&outls[(size_t)n * NC + 2 * p] = make_float2(z0 - lse, z1 - lse);
    }
}

// ---------------- Gram: G = z @ z.T  (8192 x 8192, K=16), FFMA2 inner ----------------
__global__ void __launch_bounds__(256) k_gram(float* __restrict__ out) {
    __shared__ float zrT[NC][128];
    __shared__ float zcT[NC][128];
    int tid = threadIdx.x;
    int row0 = blockIdx.y * 128;
    int col0 = blockIdx.x * 128;

    {
        int r = tid >> 1;
        int kg = (tid & 1) * 8;
        float4 v0 = *(const float4*)&g_z[(size_t)(row0 + r) * NC + kg];
        float4 v1 = *(const float4*)&g_z[(size_t)(row0 + r) * NC + kg + 4];
        zrT[kg + 0][r] = v0.x; zrT[kg + 1][r] = v0.y; zrT[kg + 2][r] = v0.z; zrT[kg + 3][r] = v0.w;
        zrT[kg + 4][r] = v1.x; zrT[kg + 5][r] = v1.y; zrT[kg + 6][r] = v1.z; zrT[kg + 7][r] = v1.w;
        float4 u0 = *(const float4*)&g_z[(size_t)(col0 + r) * NC + kg];
        float4 u1 = *(const float4*)&g_z[(size_t)(col0 + r) * NC + kg + 4];
        zcT[kg + 0][r] = u0.x; zcT[kg + 1][r] = u0.y; zcT[kg + 2][r] = u0.z; zcT[kg + 3][r] = u0.w;
        zcT[kg + 4][r] = u1.x; zcT[kg + 5][r] = u1.y; zcT[kg + 6][r] = u1.z; zcT[kg + 7][r] = u1.w;
    }
    __syncthreads();

    int ty = tid >> 4, tx = tid & 15;
    int rr = ty * 8, cc = tx * 8;
    float2 acc[8][4];
#pragma unroll
    for (int i = 0; i < 8; i++)
#pragma unroll
        for (int j = 0; j < 4; j++) acc[i][j] = make_float2(0.f, 0.f);

#pragma unroll
    for (int k = 0; k < NC; k++) {
        float4 a04 = *(const float4*)&zrT[k][rr];
        float4 a48 = *(const float4*)&zrT[k][rr + 4];
        float a[8] = {a04.x, a04.y, a04.z, a04.w, a48.x, a48.y, a48.z, a48.w};
        float4 b04 = *(const float4*)&zcT[k][cc];
        float4 b48 = *(const float4*)&zcT[k][cc + 4];
        float2 b[4] = {make_float2(b04.x, b04.y), make_float2(b04.z, b04.w),
                       make_float2(b48.x, b48.y), make_float2(b48.z, b48.w)};
#pragma unroll
        for (int i = 0; i < 8; i++) {
            float2 adup = make_float2(a[i], a[i]);
#pragma unroll
            for (int j = 0; j < 4; j++)
                acc[i][j] = ffma2(adup, b[j], acc[i][j]);
        }
    }

#pragma unroll
    for (int i = 0; i < 8; i++) {
        size_t base = (size_t)(row0 + rr + i) * NN + col0 + cc;
        float4 v0 = make_float4(acc[i][0].x, acc[i][0].y, acc[i][1].x, acc[i][1].y);
        float4 v1 = make_float4(acc[i][2].x, acc[i][2].y, acc[i][3].x, acc[i][3].y);
        *(float4*)&out[base]     = v0;
        *(float4*)&out[base + 4] = v1;
    }
}

// ---------------- launch ----------------
extern "C" void kernel_launch(void* const* d_in, const int* in_sizes, int n_in,
                              void* d_out, int out_size) {
    const float* x      = (const float*)d_in[0];
    const int*   ei     = (const int*)  d_in[1];
    const float* W1     = (const float*)d_in[2];
    const float* a_src1 = (const float*)d_in[3];
    const float* a_dst1 = (const float*)d_in[4];
    const float* b1     = (const float*)d_in[5];
    const float* W2     = (const float*)d_in[6];
    const float* a_src2 = (const float*)d_in[7];
    const float* a_dst2 = (const float*)d_in[8];
    const float* b2     = (const float*)d_in[9];
    float* out = (float*)d_out;

    k_zero_deg<<<NN / 256, 256>>>();
    k_count<<<(ETOT + 255) / 256, 256>>>(ei);
    k_scan<<<1, 1024>>>();
    k_scatter<<<(ETOT + 255) / 256, 256>>>(ei);

    k_gemm1<<<NN / 64, 256>>>(x, W1);
    k_attn_pre1<<<NN / 256, 256>>>(a_src1, a_dst1);
    k_agg1<<<NN / 8, 256>>>(b1);

    k_l2t<<<NN / 256, 256>>>(W2, a_src2, a_dst2);
    k_agg2<<<NN / 8, 256>>>(b2, out);

    k_gram<<<dim3(NN / 128, NN / 128), 256>>>(out + (size_t)NN * NC);
}

// round 4
// speedup vs baseline: 1.4704x; 1.0545x over previous
#include <cuda_runtime.h>
#include <math.h>

#define NN      8192
#define FIN     512
#define HH      8
#define C1      8
#define HC      64      // H*C1
#define NC      16
#define EE      262144
#define ETOT    (EE + NN)   // with self-loops
#define NEG     0.2f

// ---------------- packed f32x2 helpers (Blackwell FFMA2 path) ----------------
__device__ __forceinline__ float2 ffma2(float2 a, float2 b, float2 c) {
    unsigned long long ra = *reinterpret_cast<unsigned long long*>(&a);
    unsigned long long rb = *reinterpret_cast<unsigned long long*>(&b);
    unsigned long long rc = *reinterpret_cast<unsigned long long*>(&c);
    unsigned long long rd;
    asm("fma.rn.f32x2 %0, %1, %2, %3;" : "=l"(rd) : "l"(ra), "l"(rb), "l"(rc));
    return *reinterpret_cast<float2*>(&rd);
}
__device__ __forceinline__ float2 add2(float2 a, float2 b) {
    unsigned long long ra = *reinterpret_cast<unsigned long long*>(&a);
    unsigned long long rb = *reinterpret_cast<unsigned long long*>(&b);
    unsigned long long rd;
    asm("add.rn.f32x2 %0, %1, %2;" : "=l"(rd) : "l"(ra), "l"(rb));
    return *reinterpret_cast<float2*>(&rd);
}
__device__ __forceinline__ float2 shfl_xor_f2(float2 v, int m) {
    float2 r;
    r.x = __shfl_xor_sync(0xffffffffu, v.x, m);
    r.y = __shfl_xor_sync(0xffffffffu, v.y, m);
    return r;
}

// ---------------- device scratch ----------------
__device__ int   g_deg[NN];
__device__ int   g_off[NN + 1];
__device__ int   g_cur[NN];
__device__ int   g_csr[ETOT];

__device__ float g_h   [NN * HC];
__device__ float g_als1[NN * HH];
__device__ float g_ald1[NN * HH];
__device__ float g_h1  [NN * HC];
__device__ float g_h2  [NN * NC];
__device__ float g_als2[NN];
__device__ float g_ald2[NN];
__device__ float g_z   [NN * NC];

// ---------------- CSR build ----------------
__global__ void k_zero_deg() {
    int i = blockIdx.x * blockDim.x + threadIdx.x;
    if (i < NN) g_deg[i] = 1;   // self-loop pre-counted
}

__global__ void k_count(const int* __restrict__ ei) {
    int t = blockIdx.x * blockDim.x + threadIdx.x;
    if (t >= EE / 4) return;
    int4 d = __ldcs((const int4*)&ei[EE + t * 4]);
    atomicAdd(&g_deg[d.x], 1);
    atomicAdd(&g_deg[d.y], 1);
    atomicAdd(&g_deg[d.z], 1);
    atomicAdd(&g_deg[d.w], 1);
}

__global__ void k_scan() {
    __shared__ int part[1024];
    int t = threadIdx.x;
    int base = t * 8;
    int loc[8];
    int s = 0;
#pragma unroll
    for (int i = 0; i < 8; i++) { loc[i] = s; s += g_deg[base + i]; }
    part[t] = s;
    __syncthreads();
    for (int off = 1; off < 1024; off <<= 1) {
        int v = (t >= off) ? part[t - off] : 0;
        __syncthreads();
        part[t] += v;
        __syncthreads();
    }
    int pre = (t == 0) ? 0 : part[t - 1];
#pragma unroll
    for (int i = 0; i < 8; i++) {
        int o = pre + loc[i];
        g_off[base + i] = o;
        g_cur[base + i] = o;
    }
    if (t == 1023) g_off[NN] = part[1023];
}

__global__ void k_scatter(const int* __restrict__ ei) {
    int t = blockIdx.x * blockDim.x + threadIdx.x;
    if (t < EE / 4) {
        int e = t * 4;
        int4 s = __ldcs((const int4*)&ei[e]);
        int4 d = __ldcs((const int4*)&ei[EE + e]);
        g_csr[atomicAdd(&g_cur[d.x], 1)] = s.x;
        g_csr[atomicAdd(&g_cur[d.y], 1)] = s.y;
        g_csr[atomicAdd(&g_cur[d.z], 1)] = s.z;
        g_csr[atomicAdd(&g_cur[d.w], 1)] = s.w;
    } else if (t < EE / 4 + NN / 4) {
        int n0 = (t - EE / 4) * 4;
#pragma unroll
        for (int i = 0; i < 4; i++) {
            int n = n0 + i;
            g_csr[atomicAdd(&g_cur[n], 1)] = n;
        }
    }
}

// ---------------- GEMM1 + fused attention logits ----------------
// h = x @ W1 (8192x512 @ 512x64); block computes full 64-wide rows, so the
// per-node logits als1/ald1 are computed from smem in the epilogue.
__global__ void __launch_bounds__(256) k_gemm1(const float* __restrict__ x,
                                               const float* __restrict__ W1,
                                               const float* __restrict__ a_src,
                                               const float* __restrict__ a_dst) {
    __shared__ float xsT[16][68];   // transposed x tile: [k][row]
    __shared__ float ws[16][64];
    __shared__ float hs[64][68];    // epilogue: full h rows
    __shared__ float sa[2 * HC];    // a_src | a_dst
    int tid = threadIdx.x;
    int row0 = blockIdx.x * 64;
    int tr = tid >> 4;        // 0..15
    int tc = tid & 15;        // 0..15

    if (tid < 2 * HC) sa[tid] = (tid < HC) ? a_src[tid] : a_dst[tid - HC];

    float2 acc[4][2];
#pragma unroll
    for (int i = 0; i < 4; i++)
#pragma unroll
        for (int j = 0; j < 2; j++) acc[i][j] = make_float2(0.f, 0.f);

    int lr = tid >> 2, lc = (tid & 3) * 4;       // x-load: 64 rows x 4 k-groups
    int wr = tid >> 4, wc = (tid & 15) * 4;      // w-load

    for (int k0 = 0; k0 < FIN; k0 += 16) {
        float4 xv = *(const float4*)&x[(size_t)(row0 + lr) * FIN + k0 + lc];
        xsT[lc + 0][lr] = xv.x; xsT[lc + 1][lr] = xv.y;
        xsT[lc + 2][lr] = xv.z; xsT[lc + 3][lr] = xv.w;
        float4 wv = *(const float4*)&W1[(size_t)(k0 + wr) * HC + wc];
        *(float4*)&ws[wr][wc] = wv;
        __syncthreads();
#pragma unroll
        for (int kk = 0; kk < 16; kk++) {
            float4 av = *(const float4*)&xsT[kk][tr * 4];
            float4 bv = *(const float4*)&ws[kk][tc * 4];
            float2 b0 = make_float2(bv.x, bv.y);
            float2 b1 = make_float2(bv.z, bv.w);
            float a[4] = {av.x, av.y, av.z, av.w};
#pragma unroll
            for (int i = 0; i < 4; i++) {
                float2 ad = make_float2(a[i], a[i]);
                acc[i][0] = ffma2(ad, b0, acc[i][0]);
                acc[i][1] = ffma2(ad, b1, acc[i][1]);
            }
        }
        __syncthreads();
    }
#pragma unroll
    for (int i = 0; i < 4; i++) {
        int r = tr * 4 + i;
        float4 v = make_float4(acc[i][0].x, acc[i][0].y, acc[i][1].x, acc[i][1].y);
        *(float4*)&g_h[(size_t)(row0 + r) * HC + tc * 4] = v;
        *(float4*)&hs[r][tc * 4] = v;
    }
    __syncthreads();

    // epilogue: threads 0..63 compute logits for one row each
    if (tid < 64) {
        const float* hp = hs[tid];
        float als[HH], ald[HH];
#pragma unroll
        for (int h = 0; h < HH; h++) {
            float s = 0.f, d = 0.f;
#pragma unroll
            for (int c = 0; c < C1; c++) {
                float hv = hp[h * C1 + c];
                s = fmaf(hv, sa[h * C1 + c], s);
                d = fmaf(hv, sa[HC + h * C1 + c], d);
            }
            als[h] = s; ald[h] = d;
        }
        size_t b = (size_t)(row0 + tid) * HH;
        *(float4*)&g_als1[b]     = make_float4(als[0], als[1], als[2], als[3]);
        *(float4*)&g_als1[b + 4] = make_float4(als[4], als[5], als[6], als[7]);
        *(float4*)&g_ald1[b]     = make_float4(ald[0], ald[1], ald[2], ald[3]);
        *(float4*)&g_ald1[b + 4] = make_float4(ald[4], ald[5], ald[6], ald[7]);
    }
}

// ---------------- aggregation layer 1: warp per node, all heads, single pass ----------------
__global__ void k_agg1(const float* __restrict__ b1) {
    int warp = threadIdx.x >> 5;
    int lane = threadIdx.x & 31;
    int n = blockIdx.x * 8 + warp;
    int o0 = g_off[n];
    int deg = g_off[n + 1] - o0;

    float4 ad0 = *(const float4*)&g_ald1[n * HH];
    float4 ad1 = *(const float4*)&g_ald1[n * HH + 4];
    float ald[8] = {ad0.x, ad0.y, ad0.z, ad0.w, ad1.x, ad1.y, ad1.z, ad1.w};

    float2 acc[32];
#pragma unroll
    for (int i = 0; i < 32; i++) acc[i] = make_float2(0.f, 0.f);
    float sumex[8];
#pragma unroll
    for (int h = 0; h < 8; h++) sumex[h] = 0.f;

    for (int j = lane; j < deg; j += 32) {
        int s = g_csr[o0 + j];
        float4 s0 = *(const float4*)&g_als1[s * HH];
        float4 s1 = *(const float4*)&g_als1[s * HH + 4];
        float e[8] = {s0.x, s0.y, s0.z, s0.w, s1.x, s1.y, s1.z, s1.w};
        float ex[8];
#pragma unroll
        for (int h = 0; h < 8; h++) {
            float v = e[h] + ald[h];
            v = fmaxf(v, NEG * v);      // leaky relu (valid since NEG < 1)
            ex[h] = __expf(v);
            sumex[h] += ex[h];
        }
        const float4* hp = (const float4*)&g_h[(size_t)s * HC];
#pragma unroll
        for (int h = 0; h < 8; h++) {
            float2 exd = make_float2(ex[h], ex[h]);
            float4 h0 = hp[h * 2 + 0];
            float4 h1 = hp[h * 2 + 1];
            acc[h * 4 + 0] = ffma2(exd, make_float2(h0.x, h0.y), acc[h * 4 + 0]);
            acc[h * 4 + 1] = ffma2(exd, make_float2(h0.z, h0.w), acc[h * 4 + 1]);
            acc[h * 4 + 2] = ffma2(exd, make_float2(h1.x, h1.y), acc[h * 4 + 2]);
            acc[h * 4 + 3] = ffma2(exd, make_float2(h1.z, h1.w), acc[h * 4 + 3]);
        }
    }

    // reduce-scatter: after 5 steps lane l owns channel pair {2l, 2l+1} in acc[0]
    {
#pragma unroll
        for (int i = 0; i < 16; i++) {
            bool hi = (lane & 16) != 0;
            float2 send = hi ? acc[i] : acc[i + 16];
            float2 got = shfl_xor_f2(send, 16);
            float2 keep = hi ? acc[i + 16] : acc[i];
            acc[i] = add2(keep, got);
        }
#pragma unroll
        for (int i = 0; i < 8; i++) {
            bool hi = (lane & 8) != 0;
            float2 send = hi ? acc[i] : acc[i + 8];
            float2 got = shfl_xor_f2(send, 8);
            float2 keep = hi ? acc[i + 8] : acc[i];
            acc[i] = add2(keep, got);
        }
#pragma unroll
        for (int i = 0; i < 4; i++) {
            bool hi = (lane & 4) != 0;
            float2 send = hi ? acc[i] : acc[i + 4];
            float2 got = shfl_xor_f2(send, 4);
            float2 keep = hi ? acc[i + 4] : acc[i];
            acc[i] = add2(keep, got);
        }
#pragma unroll
        for (int i = 0; i < 2; i++) {
            bool hi = (lane & 2) != 0;
            float2 send = hi ? acc[i] : acc[i + 2];
            float2 got = shfl_xor_f2(send, 2);
            float2 keep = hi ? acc[i + 2] : acc[i];
            acc[i] = add2(keep, got);
        }
        {
            bool hi = (lane & 1) != 0;
            float2 send = hi ? acc[0] : acc[1];
            float2 got = shfl_xor_f2(send, 1);
            float2 keep = hi ? acc[1] : acc[0];
            acc[0] = add2(keep, got);
        }
    }

    // sumex reduce-scatter over heads (bits 4,3,2), then full-add over bits 1,0
    {
#pragma unroll
        for (int i = 0; i < 4; i++) {
            bool hi = (lane & 16) != 0;
            float send = hi ? sumex[i] : sumex[i + 4];
            float got = __shfl_xor_sync(0xffffffffu, send, 16);
            float keep = hi ? sumex[i + 4] : sumex[i];
            sumex[i] = keep + got;
        }
#pragma unroll
        for (int i = 0; i < 2; i++) {
            bool hi = (lane & 8) != 0;
            float send = hi ? sumex[i] : sumex[i + 2];
            float got = __shfl_xor_sync(0xffffffffu, send, 8);
            float keep = hi ? sumex[i + 2] : sumex[i];
            sumex[i] = keep + got;
        }
        {
            bool hi = (lane & 4) != 0;
            float send = hi ? sumex[0] : sumex[1];
            float got = __shfl_xor_sync(0xffffffffu, send, 4);
            float keep = hi ? sumex[1] : sumex[0];
            sumex[0] = keep + got;
        }
    }
    float se = sumex[0];
    se += __shfl_xor_sync(0xffffffffu, se, 2);
    se += __shfl_xor_sync(0xffffffffu, se, 1);

    float inv = 1.f / se;
    float c0 = acc[0].x * inv + b1[2 * lane];
    float c1 = acc[0].y * inv + b1[2 * lane + 1];
    c0 = (c0 > 0.f) ? c0 : (__expf(c0) - 1.f);   // ELU
    c1 = (c1 > 0.f) ? c1 : (__expf(c1) - 1.f);
    *(float2*)&g_h1[(size_t)n * HC + 2 * lane] = make_float2(c0, c1);
}

// ---------------- layer 2 transform + logits ----------------
__global__ void k_l2t(const float* __restrict__ W2,
                      const float* __restrict__ a_src2, const float* __restrict__ a_dst2) {
    __shared__ float w[HC * NC];
    __shared__ float as2[NC], ad2[NC];
    for (int i = threadIdx.x; i < HC * NC; i += blockDim.x) w[i] = W2[i];
    if (threadIdx.x < NC) { as2[threadIdx.x] = a_src2[threadIdx.x]; ad2[threadIdx.x] = a_dst2[threadIdx.x]; }
    __syncthreads();
    int n = blockIdx.x * blockDim.x + threadIdx.x;
    if (n >= NN) return;
    const float* hp = &g_h1[(size_t)n * HC];
    float out[NC];
#pragma unroll
    for (int c = 0; c < NC; c++) out[c] = 0.f;
#pragma unroll 8
    for (int k = 0; k < HC; k++) {
        float hv = hp[k];
#pragma unroll
        for (int c = 0; c < NC; c++) out[c] = fmaf(hv, w[k * NC + c], out[c]);
    }
    float s = 0.f, d = 0.f;
#pragma unroll
    for (int c = 0; c < NC; c++) {
        g_h2[(size_t)n * NC + c] = out[c];
        s = fmaf(out[c], as2[c], s);
        d = fmaf(out[c], ad2[c], d);
    }
    g_als2[n] = s;
    g_ald2[n] = d;
}

// ---------------- layer 2 aggregation + log_softmax fused ----------------
__global__ void k_agg2(const float* __restrict__ b2, float* __restrict__ outls) {
    int warp = threadIdx.x >> 5;
    int lane = threadIdx.x & 31;
    int n = blockIdx.x * 8 + warp;
    int o0 = g_off[n];
    int deg = g_off[n + 1] - o0;
    float ald = g_ald2[n];

    float2 acc[8];
#pragma unroll
    for (int i = 0; i < 8; i++) acc[i] = make_float2(0.f, 0.f);
    float sumex = 0.f;

    for (int j = lane; j < deg; j += 32) {
        int s = g_csr[o0 + j];
        float v = g_als2[s] + ald;
        v = fmaxf(v, NEG * v);
        float ex = __expf(v);
        sumex += ex;
        float2 exd = make_float2(ex, ex);
        const float4* hp = (const float4*)&g_h2[(size_t)s * NC];
#pragma unroll
        for (int q = 0; q < 4; q++) {
            float4 hv = hp[q];
            acc[q * 2 + 0] = ffma2(exd, make_float2(hv.x, hv.y), acc[q * 2 + 0]);
            acc[q * 2 + 1] = ffma2(exd, make_float2(hv.z, hv.w), acc[q * 2 + 1]);
        }
    }

    {
#pragma unroll
        for (int i = 0; i < 4; i++) {
            bool hi = (lane & 16) != 0;
            float2 send = hi ? acc[i] : acc[i + 4];
            float2 got = shfl_xor_f2(send, 16);
            float2 keep = hi ? acc[i + 4] : acc[i];
            acc[i] = add2(keep, got);
        }
#pragma unroll
        for (int i = 0; i < 2; i++) {
            bool hi = (lane & 8) != 0;
            float2 send = hi ? acc[i] : acc[i + 2];
            float2 got = shfl_xor_f2(send, 8);
            float2 keep = hi ? acc[i + 2] : acc[i];
            acc[i] = add2(keep, got);
        }
        {
            bool hi = (lane & 4) != 0;
            float2 send = hi ? acc[0] : acc[1];
            float2 got = shfl_xor_f2(send, 4);
            float2 keep = hi ? acc[1] : acc[0];
            acc[0] = add2(keep, got);
        }
    }
    acc[0] = add2(acc[0], shfl_xor_f2(acc[0], 2));
    acc[0] = add2(acc[0], shfl_xor_f2(acc[0], 1));

#pragma unroll
    for (int o = 16; o >= 1; o >>= 1) sumex += __shfl_xor_sync(0xffffffffu, sumex, o);

    int p = lane >> 2;
    float inv = 1.f / sumex;
    float z0 = acc[0].x * inv + b2[2 * p];
    float z1 = acc[0].y * inv + b2[2 * p + 1];

    float m = fmaxf(z0, z1);
#pragma unroll
    for (int o = 16; o >= 1; o >>= 1) m = fmaxf(m, __shfl_xor_sync(0xffffffffu, m, o));
    float se2 = __expf(z0 - m) + __expf(z1 - m);
#pragma unroll
    for (int o = 16; o >= 1; o >>= 1) se2 += __shfl_xor_sync(0xffffffffu, se2, o);
    se2 *= 0.25f;
    float lse = m + __logf(se2);

    if ((lane & 3) == 0) {
        *(float2*)&g_z[(size_t)n * NC + 2 * p] = make_float2(z0, z1);
        *(float2*)&outls[(size_t)n * NC + 2 * p] = make_float2(z0 - lse, z1 - lse);
    }
}

// ---------------- Gram: G = z @ z.T, FFMA2 inner, streaming stores ----------------
__global__ void __launch_bounds__(256) k_gram(float* __restrict__ out) {
    __shared__ float zrT[NC][128];
    __shared__ float zcT[NC][128];
    int tid = threadIdx.x;
    int row0 = blockIdx.y * 128;
    int col0 = blockIdx.x * 128;

    {
        int r = tid >> 1;
        int kg = (tid & 1) * 8;
        float4 v0 = *(const float4*)&g_z[(size_t)(row0 + r) * NC + kg];
        float4 v1 = *(const float4*)&g_z[(size_t)(row0 + r) * NC + kg + 4];
        zrT[kg + 0][r] = v0.x; zrT[kg + 1][r] = v0.y; zrT[kg + 2][r] = v0.z; zrT[kg + 3][r] = v0.w;
        zrT[kg + 4][r] = v1.x; zrT[kg + 5][r] = v1.y; zrT[kg + 6][r] = v1.z; zrT[kg + 7][r] = v1.w;
        float4 u0 = *(const float4*)&g_z[(size_t)(col0 + r) * NC + kg];
        float4 u1 = *(const float4*)&g_z[(size_t)(col0 + r) * NC + kg + 4];
        zcT[kg + 0][r] = u0.x; zcT[kg + 1][r] = u0.y; zcT[kg + 2][r] = u0.z; zcT[kg + 3][r] = u0.w;
        zcT[kg + 4][r] = u1.x; zcT[kg + 5][r] = u1.y; zcT[kg + 6][r] = u1.z; zcT[kg + 7][r] = u1.w;
    }
    __syncthreads();

    int ty = tid >> 4, tx = tid & 15;
    int rr = ty * 8, cc = tx * 8;
    float2 acc[8][4];
#pragma unroll
    for (int i = 0; i < 8; i++)
#pragma unroll
        for (int j = 0; j < 4; j++) acc[i][j] = make_float2(0.f, 0.f);

#pragma unroll
    for (int k = 0; k < NC; k++) {
        float4 a04 = *(const float4*)&zrT[k][rr];
        float4 a48 = *(const float4*)&zrT[k][rr + 4];
        float a[8] = {a04.x, a04.y, a04.z, a04.w, a48.x, a48.y, a48.z, a48.w};
        float4 b04 = *(const float4*)&zcT[k][cc];
        float4 b48 = *(const float4*)&zcT[k][cc + 4];
        float2 b[4] = {make_float2(b04.x, b04.y), make_float2(b04.z, b04.w),
                       make_float2(b48.x, b48.y), make_float2(b48.z, b48.w)};
#pragma unroll
        for (int i = 0; i < 8; i++) {
            float2 adup = make_float2(a[i], a[i]);
#pragma unroll
            for (int j = 0; j < 4; j++)
                acc[i][j] = ffma2(adup, b[j], acc[i][j]);
        }
    }

#pragma unroll
    for (int i = 0; i < 8; i++) {
        size_t base = (size_t)(row0 + rr + i) * NN + col0 + cc;
        float4 v0 = make_float4(acc[i][0].x, acc[i][0].y, acc[i][1].x, acc[i][1].y);
        float4 v1 = make_float4(acc[i][2].x, acc[i][2].y, acc[i][3].x, acc[i][3].y);
        __stcs((float4*)&out[base], v0);
        __stcs((float4*)&out[base + 4], v1);
    }
}

// ---------------- launch (forked-stream DAG, capture-safe) ----------------
extern "C" void kernel_launch(void* const* d_in, const int* in_sizes, int n_in,
                              void* d_out, int out_size) {
    const float* x      = (const float*)d_in[0];
    const int*   ei     = (const int*)  d_in[1];
    const float* W1     = (const float*)d_in[2];
    const float* a_src1 = (const float*)d_in[3];
    const float* a_dst1 = (const float*)d_in[4];
    const float* b1     = (const float*)d_in[5];
    const float* W2     = (const float*)d_in[6];
    const float* a_src2 = (const float*)d_in[7];
    const float* a_dst2 = (const float*)d_in[8];
    const float* b2     = (const float*)d_in[9];
    float* out = (float*)d_out;

    static cudaStream_t sA = nullptr;
    static cudaEvent_t evFork = nullptr, evA = nullptr;
    if (sA == nullptr) {
        cudaStreamCreateWithFlags(&sA, cudaStreamNonBlocking);
        cudaEventCreateWithFlags(&evFork, cudaEventDisableTiming);
        cudaEventCreateWithFlags(&evA, cudaEventDisableTiming);
    }

    // fork: CSR build on sA, GEMM1 on main stream
    cudaEventRecord(evFork, 0);
    cudaStreamWaitEvent(sA, evFork, 0);

    k_zero_deg<<<NN / 256, 256, 0, sA>>>();
    k_count<<<(EE / 4 + 255) / 256, 256, 0, sA>>>(ei);
    k_scan<<<1, 1024, 0, sA>>>();
    k_scatter<<<((EE + NN) / 4 + 255) / 256, 256, 0, sA>>>(ei);
    cudaEventRecord(evA, sA);

    k_gemm1<<<NN / 64, 256>>>(x, W1, a_src1, a_dst1);

    // join
    cudaStreamWaitEvent(0, evA, 0);

    k_agg1<<<NN / 8, 256>>>(b1);
    k_l2t<<<NN / 256, 256>>>(W2, a_src2, a_dst2);
    k_agg2<<<NN / 8, 256>>>(b2, out);
    k_gram<<<dim3(NN / 128, NN / 128), 256>>>(out + (size_t)NN * NC);
}

// round 5
// speedup vs baseline: 1.6827x; 1.1444x over previous
#include <cuda_runtime.h>
#include <math.h>

#define NN      8192
#define FIN     512
#define HH      8
#define C1      8
#define HC      64      // H*C1
#define NC      16
#define EE      262144
#define ETOT    (EE + NN)
#define NEG     0.2f

// ---------------- packed f32x2 helpers ----------------
__device__ __forceinline__ float2 ffma2(float2 a, float2 b, float2 c) {
    unsigned long long ra = *reinterpret_cast<unsigned long long*>(&a);
    unsigned long long rb = *reinterpret_cast<unsigned long long*>(&b);
    unsigned long long rc = *reinterpret_cast<unsigned long long*>(&c);
    unsigned long long rd;
    asm("fma.rn.f32x2 %0, %1, %2, %3;" : "=l"(rd) : "l"(ra), "l"(rb), "l"(rc));
    return *reinterpret_cast<float2*>(&rd);
}
__device__ __forceinline__ float2 add2(float2 a, float2 b) {
    unsigned long long ra = *reinterpret_cast<unsigned long long*>(&a);
    unsigned long long rb = *reinterpret_cast<unsigned long long*>(&b);
    unsigned long long rd;
    asm("add.rn.f32x2 %0, %1, %2;" : "=l"(rd) : "l"(ra), "l"(rb));
    return *reinterpret_cast<float2*>(&rd);
}
__device__ __forceinline__ float2 shfl_xor_f2(float2 v, int m) {
    float2 r;
    r.x = __shfl_xor_sync(0xffffffffu, v.x, m);
    r.y = __shfl_xor_sync(0xffffffffu, v.y, m);
    return r;
}

// ---------------- device scratch ----------------
__device__ int   g_deg[NN];
__device__ int   g_off[NN + 1];
__device__ int   g_cur[NN];
__device__ int   g_csr[ETOT];

__device__ float g_h   [NN * HC];
__device__ float g_als1[NN * HH];
__device__ float g_ald1[NN * HH];
__device__ float g_h2  [NN * NC];
__device__ float g_als2[NN];
__device__ float g_ald2[NN];
__device__ float g_z   [NN * NC];

// ---------------- CSR build ----------------
__global__ void k_zero_deg() {
    int i = blockIdx.x * blockDim.x + threadIdx.x;
    if (i < NN) g_deg[i] = 1;   // self-loop pre-counted
}

__global__ void k_count(const int* __restrict__ ei) {
    int t = blockIdx.x * blockDim.x + threadIdx.x;
    if (t >= EE / 4) return;
    int4 d = __ldcs((const int4*)&ei[EE + t * 4]);
    atomicAdd(&g_deg[d.x], 1);
    atomicAdd(&g_deg[d.y], 1);
    atomicAdd(&g_deg[d.z], 1);
    atomicAdd(&g_deg[d.w], 1);
}

__global__ void k_scan() {   // 1024 threads, warp-shuffle scan
    __shared__ int wsum[32];
    int t = threadIdx.x;
    int lane = t & 31, w = t >> 5;
    int base = t * 8;
    int loc[8];
    int s = 0;
#pragma unroll
    for (int i = 0; i < 8; i++) { loc[i] = s; s += g_deg[base + i]; }
    int v = s;   // inclusive warp scan
#pragma unroll
    for (int o = 1; o < 32; o <<= 1) {
        int u = __shfl_up_sync(0xffffffffu, v, o);
        if (lane >= o) v += u;
    }
    if (lane == 31) wsum[w] = v;
    __syncthreads();
    if (w == 0) {
        int ws = wsum[lane];
#pragma unroll
        for (int o = 1; o < 32; o <<= 1) {
            int u = __shfl_up_sync(0xffffffffu, ws, o);
            if (lane >= o) ws += u;
        }
        wsum[lane] = ws;
    }
    __syncthreads();
    int pre = ((w == 0) ? 0 : wsum[w - 1]) + v - s;  // exclusive prefix for this thread
#pragma unroll
    for (int i = 0; i < 8; i++) {
        int o = pre + loc[i];
        g_off[base + i] = o;
        g_cur[base + i] = o;
    }
    if (t == 1023) g_off[NN] = wsum[31];
}

__global__ void k_scatter(const int* __restrict__ ei) {
    int t = blockIdx.x * blockDim.x + threadIdx.x;
    if (t < EE / 4) {
        int e = t * 4;
        int4 s = __ldcs((const int4*)&ei[e]);
        int4 d = __ldcs((const int4*)&ei[EE + e]);
        g_csr[atomicAdd(&g_cur[d.x], 1)] = s.x;
        g_csr[atomicAdd(&g_cur[d.y], 1)] = s.y;
        g_csr[atomicAdd(&g_cur[d.z], 1)] = s.z;
        g_csr[atomicAdd(&g_cur[d.w], 1)] = s.w;
    } else if (t < EE / 4 + NN / 4) {
        int n0 = (t - EE / 4) * 4;
#pragma unroll
        for (int i = 0; i < 4; i++) {
            int n = n0 + i;
            g_csr[atomicAdd(&g_cur[n], 1)] = n;
        }
    }
}

// ---------------- GEMM1 + fused attention logits ----------------
__global__ void __launch_bounds__(256) k_gemm1(const float* __restrict__ x,
                                               const float* __restrict__ W1,
                                               const float* __restrict__ a_src,
                                               const float* __restrict__ a_dst) {
    __shared__ float xsT[16][68];
    __shared__ float ws[16][64];
    __shared__ float hs[64][68];
    __shared__ float sa[2 * HC];
    int tid = threadIdx.x;
    int row0 = blockIdx.x * 64;
    int tr = tid >> 4;
    int tc = tid & 15;

    if (tid < 2 * HC) sa[tid] = (tid < HC) ? a_src[tid] : a_dst[tid - HC];

    float2 acc[4][2];
#pragma unroll
    for (int i = 0; i < 4; i++)
#pragma unroll
        for (int j = 0; j < 2; j++) acc[i][j] = make_float2(0.f, 0.f);

    int lr = tid >> 2, lc = (tid & 3) * 4;
    int wr = tid >> 4, wc = (tid & 15) * 4;

    for (int k0 = 0; k0 < FIN; k0 += 16) {
        float4 xv = *(const float4*)&x[(size_t)(row0 + lr) * FIN + k0 + lc];
        xsT[lc + 0][lr] = xv.x; xsT[lc + 1][lr] = xv.y;
        xsT[lc + 2][lr] = xv.z; xsT[lc + 3][lr] = xv.w;
        float4 wv = *(const float4*)&W1[(size_t)(k0 + wr) * HC + wc];
        *(float4*)&ws[wr][wc] = wv;
        __syncthreads();
#pragma unroll
        for (int kk = 0; kk < 16; kk++) {
            float4 av = *(const float4*)&xsT[kk][tr * 4];
            float4 bv = *(const float4*)&ws[kk][tc * 4];
            float2 b0 = make_float2(bv.x, bv.y);
            float2 b1 = make_float2(bv.z, bv.w);
            float a[4] = {av.x, av.y, av.z, av.w};
#pragma unroll
            for (int i = 0; i < 4; i++) {
                float2 ad = make_float2(a[i], a[i]);
                acc[i][0] = ffma2(ad, b0, acc[i][0]);
                acc[i][1] = ffma2(ad, b1, acc[i][1]);
            }
        }
        __syncthreads();
    }
#pragma unroll
    for (int i = 0; i < 4; i++) {
        int r = tr * 4 + i;
        float4 v = make_float4(acc[i][0].x, acc[i][0].y, acc[i][1].x, acc[i][1].y);
        *(float4*)&g_h[(size_t)(row0 + r) * HC + tc * 4] = v;
        *(float4*)&hs[r][tc * 4] = v;
    }
    __syncthreads();

    if (tid < 64) {
        const float* hp = hs[tid];
        float als[HH], ald[HH];
#pragma unroll
        for (int h = 0; h < HH; h++) {
            float s = 0.f, d = 0.f;
#pragma unroll
            for (int c = 0; c < C1; c++) {
                float hv = hp[h * C1 + c];
                s = fmaf(hv, sa[h * C1 + c], s);
                d = fmaf(hv, sa[HC + h * C1 + c], d);
            }
            als[h] = s; ald[h] = d;
        }
        size_t b = (size_t)(row0 + tid) * HH;
        *(float4*)&g_als1[b]     = make_float4(als[0], als[1], als[2], als[3]);
        *(float4*)&g_als1[b + 4] = make_float4(als[4], als[5], als[6], als[7]);
        *(float4*)&g_ald1[b]     = make_float4(ald[0], ald[1], ald[2], ald[3]);
        *(float4*)&g_ald1[b + 4] = make_float4(ald[4], ald[5], ald[6], ald[7]);
    }
}

// ---------------- fused agg1 + layer2 transform ----------------
// Block = 256 threads = 8 warps = 2 nodes x 4 warps; each warp handles 2 heads
// (16 channels). After aggregation+ELU, h1 lives in smem; the same block then
// computes h2 = h1 @ W2 and the layer-2 logits. g_h1 never exists in global.
__global__ void __launch_bounds__(256) k_agg1(const float* __restrict__ b1,
                                              const float* __restrict__ W2,
                                              const float* __restrict__ a_src2,
                                              const float* __restrict__ a_dst2) {
    __shared__ float h1s[2][HC];
    __shared__ float w2s[HC * NC];
    int tid = threadIdx.x;
    for (int i = tid; i < HC * NC; i += 256) w2s[i] = W2[i];

    int warp = tid >> 5;
    int lane = tid & 31;
    int nl = warp >> 2;                 // local node 0/1
    int hp = warp & 3;                  // head-pair: heads {2hp, 2hp+1}, channels hp*16..hp*16+15
    int n = blockIdx.x * 2 + nl;
    int o0 = g_off[n];
    int deg = g_off[n + 1] - o0;

    float2 aldv = *(const float2*)&g_ald1[n * HH + 2 * hp];

    float2 acc[8];
#pragma unroll
    for (int i = 0; i < 8; i++) acc[i] = make_float2(0.f, 0.f);
    float sum0 = 0.f, sum1 = 0.f;

    for (int j = lane; j < deg; j += 32) {
        int s = g_csr[o0 + j];
        float2 alsv = *(const float2*)&g_als1[s * HH + 2 * hp];
        float v0 = alsv.x + aldv.x;
        float v1 = alsv.y + aldv.y;
        v0 = fmaxf(v0, NEG * v0);
        v1 = fmaxf(v1, NEG * v1);
        float ex0 = __expf(v0);
        float ex1 = __expf(v1);
        sum0 += ex0; sum1 += ex1;
        const float4* hpnt = (const float4*)&g_h[(size_t)s * HC + hp * 16];
        float4 q0 = hpnt[0], q1 = hpnt[1], q2 = hpnt[2], q3 = hpnt[3];
        float2 e0 = make_float2(ex0, ex0);
        float2 e1 = make_float2(ex1, ex1);
        acc[0] = ffma2(e0, make_float2(q0.x, q0.y), acc[0]);
        acc[1] = ffma2(e0, make_float2(q0.z, q0.w), acc[1]);
        acc[2] = ffma2(e0, make_float2(q1.x, q1.y), acc[2]);
        acc[3] = ffma2(e0, make_float2(q1.z, q1.w), acc[3]);
        acc[4] = ffma2(e1, make_float2(q2.x, q2.y), acc[4]);
        acc[5] = ffma2(e1, make_float2(q2.z, q2.w), acc[5]);
        acc[6] = ffma2(e1, make_float2(q3.x, q3.y), acc[6]);
        acc[7] = ffma2(e1, make_float2(q3.z, q3.w), acc[7]);
    }

    // reduce-scatter 8 float2 over bits 4,3,2; full-add over bits 1,0
    {
#pragma unroll
        for (int i = 0; i < 4; i++) {
            bool hi = (lane & 16) != 0;
            float2 send = hi ? acc[i] : acc[i + 4];
            float2 got = shfl_xor_f2(send, 16);
            float2 keep = hi ? acc[i + 4] : acc[i];
            acc[i] = add2(keep, got);
        }
#pragma unroll
        for (int i = 0; i < 2; i++) {
            bool hi = (lane & 8) != 0;
            float2 send = hi ? acc[i] : acc[i + 2];
            float2 got = shfl_xor_f2(send, 8);
            float2 keep = hi ? acc[i + 2] : acc[i];
            acc[i] = add2(keep, got);
        }
        {
            bool hi = (lane & 4) != 0;
            float2 send = hi ? acc[0] : acc[1];
            float2 got = shfl_xor_f2(send, 4);
            float2 keep = hi ? acc[1] : acc[0];
            acc[0] = add2(keep, got);
        }
    }
    acc[0] = add2(acc[0], shfl_xor_f2(acc[0], 2));
    acc[0] = add2(acc[0], shfl_xor_f2(acc[0], 1));
    // lane owns pair q = (lane>>2)&7 -> warp channels {2q, 2q+1}

#pragma unroll
    for (int o = 16; o >= 1; o >>= 1) {
        sum0 += __shfl_xor_sync(0xffffffffu, sum0, o);
        sum1 += __shfl_xor_sync(0xffffffffu, sum1, o);
    }

    int q = lane >> 2;
    float inv = 1.f / ((q < 4) ? sum0 : sum1);
    int ch = hp * 16 + 2 * q;
    float c0 = acc[0].x * inv + b1[ch];
    float c1 = acc[0].y * inv + b1[ch + 1];
    c0 = (c0 > 0.f) ? c0 : (__expf(c0) - 1.f);
    c1 = (c1 > 0.f) ? c1 : (__expf(c1) - 1.f);
    if ((lane & 3) == 0)
        *(float2*)&h1s[nl][ch] = make_float2(c0, c1);
    __syncthreads();

    // layer-2 transform: 32 threads (2 nodes x 16 classes)
    if (tid < 2 * NC) {
        int tn = tid >> 4;               // local node
        int c = tid & 15;                // class
        int gn = blockIdx.x * 2 + tn;
        const float* hp1 = h1s[tn];
        float o = 0.f;
#pragma unroll
        for (int k = 0; k < HC; k++)
            o = fmaf(hp1[k], w2s[k * NC + c], o);
        g_h2[(size_t)gn * NC + c] = o;
        float sv = o * a_src2[c];
        float dv = o * a_dst2[c];
#pragma unroll
        for (int off = 8; off >= 1; off >>= 1) {
            sv += __shfl_xor_sync(0xffffffffu, sv, off);
            dv += __shfl_xor_sync(0xffffffffu, dv, off);
        }
        if (c == 0) {
            g_als2[gn] = sv;
            g_ald2[gn] = dv;
        }
    }
}

// ---------------- layer 2 aggregation + log_softmax fused ----------------
__global__ void k_agg2(const float* __restrict__ b2, float* __restrict__ outls) {
    int warp = threadIdx.x >> 5;
    int lane = threadIdx.x & 31;
    int n = blockIdx.x * 8 + warp;
    int o0 = g_off[n];
    int deg = g_off[n + 1] - o0;
    float ald = g_ald2[n];

    float2 acc[8];
#pragma unroll
    for (int i = 0; i < 8; i++) acc[i] = make_float2(0.f, 0.f);
    float sumex = 0.f;

    for (int j = lane; j < deg; j += 32) {
        int s = g_csr[o0 + j];
        float v = g_als2[s] + ald;
        v = fmaxf(v, NEG * v);
        float ex = __expf(v);
        sumex += ex;
        float2 exd = make_float2(ex, ex);
        const float4* hp = (const float4*)&g_h2[(size_t)s * NC];
#pragma unroll
        for (int qq = 0; qq < 4; qq++) {
            float4 hv = hp[qq];
            acc[qq * 2 + 0] = ffma2(exd, make_float2(hv.x, hv.y), acc[qq * 2 + 0]);
            acc[qq * 2 + 1] = ffma2(exd, make_float2(hv.z, hv.w), acc[qq * 2 + 1]);
        }
    }

    {
#pragma unroll
        for (int i = 0; i < 4; i++) {
            bool hi = (lane & 16) != 0;
            float2 send = hi ? acc[i] : acc[i + 4];
            float2 got = shfl_xor_f2(send, 16);
            float2 keep = hi ? acc[i + 4] : acc[i];
            acc[i] = add2(keep, got);
        }
#pragma unroll
        for (int i = 0; i < 2; i++) {
            bool hi = (lane & 8) != 0;
            float2 send = hi ? acc[i] : acc[i + 2];
            float2 got = shfl_xor_f2(send, 8);
            float2 keep = hi ? acc[i + 2] : acc[i];
            acc[i] = add2(keep, got);
        }
        {
            bool hi = (lane & 4) != 0;
            float2 send = hi ? acc[0] : acc[1];
            float2 got = shfl_xor_f2(send, 4);
            float2 keep = hi ? acc[1] : acc[0];
            acc[0] = add2(keep, got);
        }
    }
    acc[0] = add2(acc[0], shfl_xor_f2(acc[0], 2));
    acc[0] = add2(acc[0], shfl_xor_f2(acc[0], 1));

#pragma unroll
    for (int o = 16; o >= 1; o >>= 1) sumex += __shfl_xor_sync(0xffffffffu, sumex, o);

    int p = lane >> 2;
    float inv = 1.f / sumex;
    float z0 = acc[0].x * inv + b2[2 * p];
    float z1 = acc[0].y * inv + b2[2 * p + 1];

    float m = fmaxf(z0, z1);
#pragma unroll
    for (int o = 16; o >= 1; o >>= 1) m = fmaxf(m, __shfl_xor_sync(0xffffffffu, m, o));
    float se2 = __expf(z0 - m) + __expf(z1 - m);
#pragma unroll
    for (int o = 16; o >= 1; o >>= 1) se2 += __shfl_xor_sync(0xffffffffu, se2, o);
    se2 *= 0.25f;
    float lse = m + __logf(se2);

    if ((lane & 3) == 0) {
        *(float2*)&g_z[(size_t)n * NC + 2 * p] = make_float2(z0, z1);
        *(float2*)&outls[(size_t)n * NC + 2 * p] = make_float2(z0 - lse, z1 - lse);
    }
}

// ---------------- Gram: G = z @ z.T, FFMA2, streaming stores ----------------
__global__ void __launch_bounds__(256) k_gram(float* __restrict__ out) {
    __shared__ float zrT[NC][128];
    __shared__ float zcT[NC][128];
    int tid = threadIdx.x;
    int row0 = blockIdx.y * 128;
    int col0 = blockIdx.x * 128;

    {
        int r = tid >> 1;
        int kg = (tid & 1) * 8;
        float4 v0 = *(const float4*)&g_z[(size_t)(row0 + r) * NC + kg];
        float4 v1 = *(const float4*)&g_z[(size_t)(row0 + r) * NC + kg + 4];
        zrT[kg + 0][r] = v0.x; zrT[kg + 1][r] = v0.y; zrT[kg + 2][r] = v0.z; zrT[kg + 3][r] = v0.w;
        zrT[kg + 4][r] = v1.x; zrT[kg + 5][r] = v1.y; zrT[kg + 6][r] = v1.z; zrT[kg + 7][r] = v1.w;
        float4 u0 = *(const float4*)&g_z[(size_t)(col0 + r) * NC + kg];
        float4 u1 = *(const float4*)&g_z[(size_t)(col0 + r) * NC + kg + 4];
        zcT[kg + 0][r] = u0.x; zcT[kg + 1][r] = u0.y; zcT[kg + 2][r] = u0.z; zcT[kg + 3][r] = u0.w;
        zcT[kg + 4][r] = u1.x; zcT[kg + 5][r] = u1.y; zcT[kg + 6][r] = u1.z; zcT[kg + 7][r] = u1.w;
    }
    __syncthreads();

    int ty = tid >> 4, tx = tid & 15;
    int rr = ty * 8, cc = tx * 8;
    float2 acc[8][4];
#pragma unroll
    for (int i = 0; i < 8; i++)
#pragma unroll
        for (int j = 0; j < 4; j++) acc[i][j] = make_float2(0.f, 0.f);

#pragma unroll
    for (int k = 0; k < NC; k++) {
        float4 a04 = *(const float4*)&zrT[k][rr];
        float4 a48 = *(const float4*)&zrT[k][rr + 4];
        float a[8] = {a04.x, a04.y, a04.z, a04.w, a48.x, a48.y, a48.z, a48.w};
        float4 b04 = *(const float4*)&zcT[k][cc];
        float4 b48 = *(const float4*)&zcT[k][cc + 4];
        float2 b[4] = {make_float2(b04.x, b04.y), make_float2(b04.z, b04.w),
                       make_float2(b48.x, b48.y), make_float2(b48.z, b48.w)};
#pragma unroll
        for (int i = 0; i < 8; i++) {
            float2 adup = make_float2(a[i], a[i]);
#pragma unroll
            for (int j = 0; j < 4; j++)
                acc[i][j] = ffma2(adup, b[j], acc[i][j]);
        }
    }

#pragma unroll
    for (int i = 0; i < 8; i++) {
        size_t base = (size_t)(row0 + rr + i) * NN + col0 + cc;
        float4 v0 = make_float4(acc[i][0].x, acc[i][0].y, acc[i][1].x, acc[i][1].y);
        float4 v1 = make_float4(acc[i][2].x, acc[i][2].y, acc[i][3].x, acc[i][3].y);
        __stcs((float4*)&out[base], v0);
        __stcs((float4*)&out[base + 4], v1);
    }
}

// ---------------- launch ----------------
extern "C" void kernel_launch(void* const* d_in, const int* in_sizes, int n_in,
                              void* d_out, int out_size) {
    const float* x      = (const float*)d_in[0];
    const int*   ei     = (const int*)  d_in[1];
    const float* W1     = (const float*)d_in[2];
    const float* a_src1 = (const float*)d_in[3];
    const float* a_dst1 = (const float*)d_in[4];
    const float* b1     = (const float*)d_in[5];
    const float* W2     = (const float*)d_in[6];
    const float* a_src2 = (const float*)d_in[7];
    const float* a_dst2 = (const float*)d_in[8];
    const float* b2     = (const float*)d_in[9];
    float* out = (float*)d_out;

    static cudaStream_t sA = nullptr;
    static cudaEvent_t evFork = nullptr, evA = nullptr;
    if (sA == nullptr) {
        cudaStreamCreateWithFlags(&sA, cudaStreamNonBlocking);
        cudaEventCreateWithFlags(&evFork, cudaEventDisableTiming);
        cudaEventCreateWithFlags(&evA, cudaEventDisableTiming);
    }

    cudaEventRecord(evFork, 0);
    cudaStreamWaitEvent(sA, evFork, 0);

    k_zero_deg<<<NN / 256, 256, 0, sA>>>();
    k_count<<<(EE / 4 + 255) / 256, 256, 0, sA>>>(ei);
    k_scan<<<1, 1024, 0, sA>>>();
    k_scatter<<<((EE + NN) / 4 + 255) / 256, 256, 0, sA>>>(ei);
    cudaEventRecord(evA, sA);

    k_gemm1<<<NN / 64, 256>>>(x, W1, a_src1, a_dst1);

    cudaStreamWaitEvent(0, evA, 0);

    k_agg1<<<NN / 2, 256>>>(b1, W2, a_src2, a_dst2);
    k_agg2<<<NN / 8, 256>>>(b2, out);
    k_gram<<<dim3(NN / 128, NN / 128), 256>>>(out + (size_t)NN * NC);
}